// round 1
// baseline (speedup 1.0000x reference)
#include <cuda_runtime.h>
#include <math.h>

// Problem constants
#define BB 4
#define HH 200
#define WW 176
#define HW (HH*WW)         // 35200
#define FA 10
#define NF 5
#define NFR (BB*NF)        // 20 (b,frame) pairs
#define NPF (HW*2)         // 70400 elements per frame
#define EPSV 1e-6f
#define CAP 8192

// ---- scratch (device globals; no allocations allowed) ----
__device__ float  g_vbuf[BB*NF*NPF];     // per-frame negative loss values, 5.6MB
__device__ int    g_hist[NFR*65536];     // 16-bit-prefix histograms, 5.2MB
__device__ float  g_cand[NFR*CAP];       // threshold-bin candidates
__device__ int    g_ccount[NFR];
__device__ int    g_pcnt[NFR];           // positives per (b,frame)
__device__ int    g_prefix[NFR];         // chosen 16-bit bin
__device__ int    g_r[NFR];              // residual rank inside bin
__device__ double g_clspos, g_huber, g_num;

// monotonic float<->uint key mapping (ascending)
__device__ __forceinline__ unsigned kmap(float x){
    unsigned u = __float_as_uint(x);
    return (u & 0x80000000u) ? ~u : (u | 0x80000000u);
}
__device__ __forceinline__ float kunmap(unsigned m){
    unsigned u = (m & 0x80000000u) ? (m & 0x7FFFFFFFu) : ~m;
    return __uint_as_float(u);
}
__device__ __forceinline__ double wredd(double v){
    #pragma unroll
    for (int o=16;o;o>>=1) v += __shfl_down_sync(0xffffffffu, v, o);
    return v;
}

// ---------------- zero scratch ----------------
__global__ void k_zero(){
    int i = blockIdx.x*blockDim.x + threadIdx.x;
    if (i < NFR*65536/4) ((int4*)g_hist)[i] = make_int4(0,0,0,0);
    if (i < NFR){ g_ccount[i]=0; g_pcnt[i]=0; }
    if (i == 0){ g_clspos=0.0; g_huber=0.0; g_num=0.0; }
}

// ---------------- main pass ----------------
// one thread per spatial position (b, h*W+w); handles all 10 anchors there.
__global__ void __launch_bounds__(256) k_main(
    const float* __restrict__ rm,  const float* __restrict__ psm,
    const float* __restrict__ pos, const float* __restrict__ neg,
    const float* __restrict__ tgt)
{
    int b = blockIdx.y;
    int p = blockIdx.x*blockDim.x + threadIdx.x;
    int tid = threadIdx.x;
    __shared__ int s_cnt[NF];
    if (tid < NF) s_cnt[tid] = 0;
    __syncthreads();

    double l_cp = 0.0, l_hb = 0.0;
    if (p < HW){
        const float2* posp = (const float2*)(pos + ((size_t)b*HW + p)*FA);
        const float2* negp = (const float2*)(neg + ((size_t)b*HW + p)*FA);
        float pv[FA], nv[FA];
        #pragma unroll
        for (int i=0;i<5;i++){
            float2 a = posp[i]; pv[2*i]=a.x; pv[2*i+1]=a.y;
            float2 c = negp[i]; nv[2*i]=c.x; nv[2*i+1]=c.y;
        }
        float v[FA];
        #pragma unroll
        for (int a=0;a<FA;a++){
            float x  = psm[((size_t)(b*FA + a))*HW + p];
            float pp = 1.0f/(1.0f + expf(-x));
            float q  = 1.0f - pp;              // exact (Sterbenz), matches reference path
            float nl = logf(q + EPSV);
            v[a] = -nv[a]*nl;
            int f = a >> 1;
            unsigned m = kmap(v[a]);
            atomicAdd(&g_hist[((b*NF + f) << 16) + (int)(m >> 16)], 1);
            if (pv[a] != 0.0f){
                atomicAdd(&s_cnt[f], 1);
                l_cp -= (double)logf(pp + EPSV);
                const float* tp = tgt + (((size_t)b*HW + p)*(FA*7) + a*7);
                const float* rp = rm  + ((size_t)(b*FA*7) + a*7)*HW + p;
                #pragma unroll
                for (int j=0;j<7;j++){
                    float d = fabsf(rp[(size_t)j*HW] - tp[j]);
                    l_hb += (d < 1.0f) ? (double)(0.5f*d*d) : (double)(d - 0.5f);
                }
            }
        }
        #pragma unroll
        for (int f=0; f<NF; f++){
            float2 w2; w2.x = v[2*f]; w2.y = v[2*f+1];
            *(float2*)(g_vbuf + ((size_t)(b*NF+f))*NPF + (size_t)p*2) = w2;
        }
    }
    // block-reduce the two double sums
    double r1 = wredd(l_cp), r2 = wredd(l_hb);
    __shared__ double sA[8], sB[8];
    int lane = tid & 31, wd = tid >> 5;
    if (lane==0){ sA[wd]=r1; sB[wd]=r2; }
    __syncthreads();
    if (wd==0){
        double a = (lane<8)? sA[lane] : 0.0; a = wredd(a);
        double c = (lane<8)? sB[lane] : 0.0; c = wredd(c);
        if (lane==0){
            if (a != 0.0) atomicAdd(&g_clspos, a);
            if (c != 0.0) atomicAdd(&g_huber, c);
        }
    }
    if (tid < NF && s_cnt[tid]) atomicAdd(&g_pcnt[b*NF + tid], s_cnt[tid]);
}

// ---------------- pick threshold bin per frame ----------------
__global__ void __launch_bounds__(512) k_pick(){
    int f = blockIdx.x;
    const int* hist = g_hist + (size_t)f*65536;
    __shared__ int S[512];
    __shared__ int s_chunk, s_cum;
    __shared__ int s_bins[128];
    int tid = threadIdx.x, lane = tid & 31, wd = tid >> 5;
    // coalesced chunk sums: one warp per 128-bin chunk (int4 per lane)
    for (int c = wd; c < 512; c += 16){
        int4 h = ((const int4*)hist)[c*32 + lane];
        int s = h.x + h.y + h.z + h.w;
        #pragma unroll
        for (int o=16;o;o>>=1) s += __shfl_down_sync(0xffffffffu, s, o);
        if (lane==0) S[c] = s;
    }
    __syncthreads();
    if (tid==0){
        int k = 3*(g_pcnt[f] + 1);          // floor(3*(cnt+1)) exactly
        int cum = 0, c = 511;
        for (; c > 0; c--){ if (cum + S[c] >= k) break; cum += S[c]; }
        s_chunk = c; s_cum = cum;
    }
    __syncthreads();
    if (tid < 128) s_bins[tid] = hist[s_chunk*128 + tid];
    __syncthreads();
    if (tid==0){
        int k = 3*(g_pcnt[f] + 1);
        int cum = s_cum;
        int bin = s_chunk*128;
        for (int i=127; i>=0; i--){
            if (cum + s_bins[i] >= k){ bin = s_chunk*128 + i; break; }
            cum += s_bins[i];
        }
        g_prefix[f] = bin;
        g_r[f] = k - cum;                   // 1..count(bin)
    }
}

// ---------------- sweep: sum above-bin values, compact in-bin candidates ----------------
__global__ void __launch_bounds__(256) k_collect(){
    int f = blockIdx.y;
    int P = g_prefix[f];
    int i = blockIdx.x*blockDim.x + threadIdx.x;
    double s = 0.0;
    if (i < NPF/4){
        float4 v4 = ((const float4*)(g_vbuf + (size_t)f*NPF))[i];
        float vv[4] = {v4.x, v4.y, v4.z, v4.w};
        #pragma unroll
        for (int j=0;j<4;j++){
            unsigned m = kmap(vv[j]);
            int t = (int)(m >> 16);
            if (t > P) s += (double)vv[j];
            else if (t == P){
                int id = atomicAdd(&g_ccount[f], 1);
                if (id < CAP) g_cand[(size_t)f*CAP + id] = vv[j];
            }
        }
    }
    double r = wredd(s);
    __shared__ double sA[8];
    int lane = threadIdx.x & 31, wd = threadIdx.x >> 5;
    if (lane==0) sA[wd] = r;
    __syncthreads();
    if (wd==0){
        double a = (lane<8)? sA[lane] : 0.0; a = wredd(a);
        if (lane==0 && a != 0.0) atomicAdd(&g_num, a);
    }
}

// ---------------- exact tie-aware finish among in-bin candidates ----------------
__global__ void __launch_bounds__(256) k_finish(){
    int f = blockIdx.x;
    int n = g_ccount[f]; if (n > CAP) n = CAP;
    int r = g_r[f];
    const float* cand = g_cand + (size_t)f*CAP;
    __shared__ float s_c[CAP];
    __shared__ unsigned s_tk;
    int tid = threadIdx.x;
    for (int i = tid; i < n; i += 256) s_c[i] = cand[i];
    __syncthreads();
    // r-th largest key among candidates (ties: cgt < r <= cgt+ceq uniquely defines key)
    for (int i = tid; i < n; i += 256){
        unsigned ki = kmap(s_c[i]);
        int cgt=0, ceq=0;
        for (int j=0;j<n;j++){
            unsigned kj = kmap(s_c[j]);
            cgt += (kj > ki); ceq += (kj == ki);
        }
        if (cgt < r && r <= cgt + ceq) s_tk = ki;  // benign same-value race
    }
    __syncthreads();
    unsigned tk = s_tk;
    float tv = kunmap(tk);
    double sg = 0.0; int cg = 0;
    for (int i = tid; i < n; i += 256){
        unsigned ki = kmap(s_c[i]);
        if (ki > tk){ sg += (double)s_c[i]; cg++; }
    }
    double rs = wredd(sg);
    int rc = cg;
    #pragma unroll
    for (int o=16;o;o>>=1) rc += __shfl_down_sync(0xffffffffu, rc, o);
    __shared__ double sA[8]; __shared__ int sC[8];
    int lane = tid & 31, wd = tid >> 5;
    if (lane==0){ sA[wd]=rs; sC[wd]=rc; }
    __syncthreads();
    if (wd==0){
        double a = (lane<8)? sA[lane] : 0.0; a = wredd(a);
        int c2 = (lane<8)? sC[lane] : 0;
        #pragma unroll
        for (int o=16;o;o>>=1) c2 += __shfl_down_sync(0xffffffffu, c2, o);
        if (lane==0) atomicAdd(&g_num, a + (double)(r - c2)*(double)tv);
    }
}

// ---------------- finalize 4 scalars ----------------
__global__ void k_final(float* out){
    int cnt = 0; double den = 0.0;
    for (int f=0; f<NFR; f++){ cnt += g_pcnt[f]; den += (double)(3*(g_pcnt[f]+1)); }
    double ps   = (double)cnt + 1e-6;
    double clsp = 1.5 * g_clspos / ps;       // ALPHA
    double reg  = 2.0 * g_huber  / ps;       // GAMMA
    double clsn = 1.0 * g_num / (den + 1e-6);// BETA
    out[0] = (float)(clsp + clsn);  // conf_loss
    out[1] = (float)reg;            // reg_loss
    out[2] = (float)clsp;           // cls_pos_loss
    out[3] = (float)clsn;           // cls_neg_loss
}

extern "C" void kernel_launch(void* const* d_in, const int* in_sizes, int n_in,
                              void* d_out, int out_size)
{
    const float* rm  = (const float*)d_in[0];
    const float* psm = (const float*)d_in[1];
    const float* pos = (const float*)d_in[2];
    const float* neg = (const float*)d_in[3];
    const float* tgt = (const float*)d_in[4];
    float* out = (float*)d_out;

    k_zero<<<(NFR*65536/4 + 255)/256, 256>>>();
    dim3 g1((HW + 255)/256, BB);
    k_main<<<g1, 256>>>(rm, psm, pos, neg, tgt);
    k_pick<<<NFR, 512>>>();
    dim3 gc((NPF/4 + 255)/256, NFR);
    k_collect<<<gc, 256>>>();
    k_finish<<<NFR, 256>>>();
    k_final<<<1, 1>>>(out);
}

// round 2
// speedup vs baseline: 1.4526x; 1.4526x over previous
#include <cuda_runtime.h>
#include <math.h>

// Problem constants
#define BB 4
#define HH 200
#define WW 176
#define HW (HH*WW)         // 35200
#define FA 10
#define NF 5
#define NFR (BB*NF)        // 20 (b,frame) pairs
#define NPF (HW*2)         // 70400 elements per frame
#define EPSV 1e-6f
#define NBIN 4096
#define CAP 6144

// ---- scratch (device globals; no allocations allowed) ----
__device__ float  g_vbuf[BB*NF*NPF];     // per-frame negative loss values, 5.6MB
__device__ int    g_hist[NFR*NBIN];      // 12-bit-prefix histograms, 320KB
__device__ int    g_pcnt[NFR];           // positives per (b,frame)
__device__ double g_clspos, g_huber, g_num;

// monotonic float<->uint key mapping (ascending)
__device__ __forceinline__ unsigned kmap(float x){
    unsigned u = __float_as_uint(x);
    return (u & 0x80000000u) ? ~u : (u | 0x80000000u);
}
__device__ __forceinline__ float kunmap(unsigned m){
    unsigned u = (m & 0x80000000u) ? (m & 0x7FFFFFFFu) : ~m;
    return __uint_as_float(u);
}
__device__ __forceinline__ double wredd(double v){
    #pragma unroll
    for (int o=16;o;o>>=1) v += __shfl_down_sync(0xffffffffu, v, o);
    return v;
}

// ---------------- zero scratch ----------------
__global__ void k_zero(){
    int i = blockIdx.x*blockDim.x + threadIdx.x;
    if (i < NFR*NBIN/4) ((int4*)g_hist)[i] = make_int4(0,0,0,0);
    if (i < NFR) g_pcnt[i]=0;
    if (i == 0){ g_clspos=0.0; g_huber=0.0; g_num=0.0; }
}

// ---------------- main pass ----------------
// one thread per spatial position (b, h*W+w); handles all 10 anchors there.
__global__ void __launch_bounds__(256) k_main(
    const float* __restrict__ rm,  const float* __restrict__ psm,
    const float* __restrict__ pos, const float* __restrict__ neg,
    const float* __restrict__ tgt)
{
    __shared__ float s_pos[2560], s_neg[2560];
    __shared__ int s_cnt[NF];
    __shared__ double sA[8], sB[8];
    int b = blockIdx.y;
    int tid = threadIdx.x;
    int p0 = blockIdx.x*256;
    int npos = HW - p0; if (npos > 256) npos = 256;   // HW%256==128, stays /4
    int nq = npos*FA/4;
    const float4* sp = (const float4*)(pos + ((size_t)b*HW + p0)*FA);
    const float4* sn = (const float4*)(neg + ((size_t)b*HW + p0)*FA);
    for (int i=tid; i<nq; i+=256){
        ((float4*)s_pos)[i] = sp[i];
        ((float4*)s_neg)[i] = sn[i];
    }
    if (tid < NF) s_cnt[tid] = 0;
    __syncthreads();

    int p = p0 + tid;
    double l_cp = 0.0, l_hb = 0.0;
    if (tid < npos){
        float v[FA];
        #pragma unroll
        for (int a=0;a<FA;a++){
            float x  = psm[((size_t)(b*FA + a))*HW + p];
            float pp = 1.0f/(1.0f + expf(-x));
            float nl = logf(1.0f - pp + EPSV);
            float nv = s_neg[tid*FA + a];
            v[a] = -nv*nl;
            if (v[a] != 0.0f){                         // zeros never reach top-k
                unsigned m = kmap(v[a]);
                atomicAdd(&g_hist[((b*NF + (a>>1)) << 12) + (int)(m >> 20)], 1);
            }
            if (s_pos[tid*FA + a] != 0.0f){
                atomicAdd(&s_cnt[a>>1], 1);
                l_cp -= (double)logf(pp + EPSV);
                const float* tp = tgt + (((size_t)b*HW + p)*(FA*7) + a*7);
                const float* rp = rm  + ((size_t)(b*FA*7) + a*7)*HW + p;
                #pragma unroll
                for (int j=0;j<7;j++){
                    float d = fabsf(rp[(size_t)j*HW] - tp[j]);
                    l_hb += (d < 1.0f) ? (double)(0.5f*d*d) : (double)(d - 0.5f);
                }
            }
        }
        #pragma unroll
        for (int f=0; f<NF; f++){
            float2 w2; w2.x = v[2*f]; w2.y = v[2*f+1];
            *(float2*)(g_vbuf + ((size_t)(b*NF+f))*NPF + (size_t)p*2) = w2;
        }
    }
    // block-reduce the two double sums
    double r1 = wredd(l_cp), r2 = wredd(l_hb);
    int lane = tid & 31, wd = tid >> 5;
    if (lane==0){ sA[wd]=r1; sB[wd]=r2; }
    __syncthreads();
    if (wd==0){
        double a = (lane<8)? sA[lane] : 0.0; a = wredd(a);
        double c = (lane<8)? sB[lane] : 0.0; c = wredd(c);
        if (lane==0){
            if (a != 0.0) atomicAdd(&g_clspos, a);
            if (c != 0.0) atomicAdd(&g_huber, c);
        }
    }
    if (tid < NF && s_cnt[tid]) atomicAdd(&g_pcnt[b*NF + tid], s_cnt[tid]);
}

// hierarchical suffix scan helper over shared hist[4096] via Sc[1024]/Sw[32].
// thread 0 writes (*oP, *oR). Call with all 1024 threads; k = target rank.
__device__ __forceinline__ void scan_pick(int* hist, int* Sc, int* Sw,
                                          int k, int* oP, int* oR, int tid)
{
    int c = tid;                       // blockDim.x == 1024
    int s4 = hist[4*c] + hist[4*c+1] + hist[4*c+2] + hist[4*c+3];
    Sc[c] = s4;
    int ws = s4;
    #pragma unroll
    for (int o=16;o;o>>=1) ws += __shfl_down_sync(0xffffffffu, ws, o);
    if ((tid & 31) == 0) Sw[tid >> 5] = ws;
    __syncthreads();
    if (tid == 0){
        int cum = 0, s = 31;
        while (s > 0 && cum + Sw[s] < k){ cum += Sw[s]; s--; }
        int cc = s*32 + 31;
        while (cc > s*32 && cum + Sc[cc] < k){ cum += Sc[cc]; cc--; }
        int bb = cc*4 + 3;
        while (bb > cc*4 && cum + hist[bb] < k){ cum += hist[bb]; bb--; }
        *oP = bb; *oR = k - cum;
    }
    __syncthreads();
}

// ---------------- per-frame exact top-k sum ----------------
__global__ void __launch_bounds__(1024) k_select(){
    __shared__ int hist[NBIN];
    __shared__ int Sc[1024];
    __shared__ int Sw[32];
    __shared__ int sP, sR, sP2, sR2, s_n, s_m, s_cgt;
    __shared__ unsigned s_tk;
    __shared__ float cand[CAP];
    __shared__ float cand2[256];
    __shared__ double sD[32];

    int f = blockIdx.x, tid = threadIdx.x;
    for (int i=tid; i<NBIN; i+=1024) hist[i] = g_hist[(f<<12) + i];
    if (tid == 0){ s_n = 0; s_m = 0; s_cgt = 0; }
    __syncthreads();

    int k = 3*(g_pcnt[f] + 1);               // floor(3*(cnt+1)) exactly
    scan_pick(hist, Sc, Sw, k, &sP, &sR, tid);
    int P = sP;

    // pass over plane: sum above-bin, collect in-bin candidates
    double acc = 0.0;
    const float4* vp = (const float4*)(g_vbuf + (size_t)f*NPF);
    for (int i=tid; i<NPF/4; i+=1024){
        float4 q = vp[i];
        float vv[4] = {q.x, q.y, q.z, q.w};
        #pragma unroll
        for (int j=0;j<4;j++){
            float v = vv[j];
            if (v != 0.0f){
                int t = (int)(kmap(v) >> 20);
                if (t > P) acc += (double)v;
                else if (t == P){
                    int id = atomicAdd(&s_n, 1);
                    if (id < CAP) cand[id] = v;
                }
            }
        }
    }
    __syncthreads();
    int n = s_n; if (n > CAP) n = CAP;

    // level-2 refinement on candidates: next 12 key bits
    for (int i=tid; i<NBIN; i+=1024) hist[i] = 0;
    __syncthreads();
    for (int i=tid; i<n; i+=1024)
        atomicAdd(&hist[(kmap(cand[i]) >> 8) & 0xFFF], 1);
    __syncthreads();
    scan_pick(hist, Sc, Sw, sR, &sP2, &sR2, tid);
    int P2 = sP2;

    for (int i=tid; i<n; i+=1024){
        float v = cand[i];
        int t = (int)((kmap(v) >> 8) & 0xFFF);
        if (t > P2) acc += (double)v;
        else if (t == P2){
            int id = atomicAdd(&s_m, 1);
            if (id < 256) cand2[id] = v;
        }
    }
    __syncthreads();
    int m = s_m; if (m > 256) m = 256;
    int r2 = sR2;

    // exact tie-aware finish on tiny candidate set
    for (int i=tid; i<m; i+=1024){
        unsigned ki = kmap(cand2[i]);
        int cgt = 0, ceq = 0;
        for (int j=0;j<m;j++){
            unsigned kj = kmap(cand2[j]);
            cgt += (kj > ki); ceq += (kj == ki);
        }
        if (cgt < r2 && r2 <= cgt + ceq) s_tk = ki;   // benign same-value race
    }
    __syncthreads();
    unsigned tk = s_tk;
    int cl = 0;
    for (int i=tid; i<m; i+=1024){
        unsigned ki = kmap(cand2[i]);
        if (ki > tk){ acc += (double)cand2[i]; cl++; }
    }
    if (cl) atomicAdd(&s_cgt, cl);
    __syncthreads();
    if (tid == 0) acc += (double)(r2 - s_cgt) * (double)kunmap(tk);

    // block reduce acc (32 warps) -> g_num
    double r = wredd(acc);
    if ((tid & 31) == 0) sD[tid >> 5] = r;
    __syncthreads();
    if (tid < 32){
        double a = sD[tid];
        a = wredd(a);
        if (tid == 0) atomicAdd(&g_num, a);
    }
}

// ---------------- finalize 4 scalars ----------------
__global__ void k_final(float* out){
    int cnt = 0; double den = 0.0;
    for (int f=0; f<NFR; f++){ cnt += g_pcnt[f]; den += (double)(3*(g_pcnt[f]+1)); }
    double ps   = (double)cnt + 1e-6;
    double clsp = 1.5 * g_clspos / ps;        // ALPHA
    double reg  = 2.0 * g_huber  / ps;        // GAMMA
    double clsn = 1.0 * g_num / (den + 1e-6); // BETA
    out[0] = (float)(clsp + clsn);  // conf_loss
    out[1] = (float)reg;            // reg_loss
    out[2] = (float)clsp;           // cls_pos_loss
    out[3] = (float)clsn;           // cls_neg_loss
}

extern "C" void kernel_launch(void* const* d_in, const int* in_sizes, int n_in,
                              void* d_out, int out_size)
{
    const float* rm  = (const float*)d_in[0];
    const float* psm = (const float*)d_in[1];
    const float* pos = (const float*)d_in[2];
    const float* neg = (const float*)d_in[3];
    const float* tgt = (const float*)d_in[4];
    float* out = (float*)d_out;

    k_zero<<<(NFR*NBIN/4 + 255)/256, 256>>>();
    dim3 g1((HW + 255)/256, BB);
    k_main<<<g1, 256>>>(rm, psm, pos, neg, tgt);
    k_select<<<NFR, 1024>>>();
    k_final<<<1, 1>>>(out);
}